// round 7
// baseline (speedup 1.0000x reference)
#include <cuda_runtime.h>

#define BATCH  32768
#define NPG    54
#define EPG    144
#define GLOB   10
#define CPAD   240   // padded row stride for g_concat ([226,240) always zero)
#define EDGES_TOTAL (BATCH*EPG)
#define TB     128   // rows per CTA in out-MLP GEMM
#define GPC    8     // graphs per conv CTA (32768 = 4096 * 8)
#define KP     40    // k-panel size (240 = 6 * 40)
#define NPAN   6

// Scratch for the [B, 240] padded concat activations (device global, zero-init).
static __device__ __align__(16) float g_concat[(size_t)BATCH * CPAD];
// Zero-padded Wo1: rows [0,226) written each call, rows [226,240) stay zero.
static __device__ __align__(16) float g_Wo1p[CPAD * 128];

typedef unsigned long long u64;

// ---------------- packed f32x2 helpers (sm_103a) ----------------
__device__ __forceinline__ u64 pk(float lo, float hi) {
    u64 r; asm("mov.b64 %0, {%1,%2};" : "=l"(r) : "f"(lo), "f"(hi)); return r;
}
__device__ __forceinline__ u64 f2fma(u64 a, u64 b, u64 c) {
    u64 d; asm("fma.rn.f32x2 %0, %1, %2, %3;" : "=l"(d) : "l"(a), "l"(b), "l"(c));
    return d;
}
__device__ __forceinline__ void upk(u64 v, float& lo, float& hi) {
    asm("mov.b64 {%0,%1}, %2;" : "=f"(lo), "=f"(hi) : "l"(v));
}

// ---------------- cp.async helpers ----------------
__device__ __forceinline__ void cpa16(void* s, const void* g) {
    unsigned ss = (unsigned)__cvta_generic_to_shared(s);
    asm volatile("cp.async.ca.shared.global [%0], [%1], 16;\n" :: "r"(ss), "l"(g));
}
#define CP_COMMIT() asm volatile("cp.async.commit_group;\n" ::: "memory")
#define CP_WAIT0()  asm volatile("cp.async.wait_group 0;\n" ::: "memory")

// ---------------------------------------------------------------------------
// Prologue: copy Wo1 into zero-padded g_Wo1p (rows >= 226 remain zero).
// ---------------------------------------------------------------------------
__global__ __launch_bounds__(256) void padw_kernel(const float* __restrict__ Wo1)
{
    int i = blockIdx.x * 256 + threadIdx.x;
    if (i < 226 * 128) g_Wo1p[i] = Wo1[i];
}

// ---------------------------------------------------------------------------
// Kernel A: persistent fused GraphConv1 -> relu -> GraphConv2 -> relu,
// plus the per-graph global MLP (10->8->8->10) as a one-shot phase.
// 4096 CTAs x 128 threads, GPC=8 graphs each, cp.async double-buffered inputs.
// CSR built once per graph; both aggregations are atomic-free gathers.
// ---------------------------------------------------------------------------
__global__ __launch_bounds__(128) void conv_kernel(
    const float* __restrict__ x,      const int*   __restrict__ eidx,
    const float* __restrict__ eattr,  const float* __restrict__ gfeat,
    const float* __restrict__ W_rel1, const float* __restrict__ b1,
    const float* __restrict__ W_root1,
    const float* __restrict__ W_rel2, const float* __restrict__ b2,
    const float* __restrict__ W_root2,
    const float* __restrict__ Wg1, const float* __restrict__ bg1,
    const float* __restrict__ Wg2, const float* __restrict__ bg2,
    const float* __restrict__ Wg3, const float* __restrict__ bg3)
{
    __shared__ __align__(16) float xbuf[2][NPG * 8];
    __shared__ __align__(16) int   sbuf[2][EPG];
    __shared__ __align__(16) int   dbuf[2][EPG];
    __shared__ __align__(16) float ebuf[2][EPG];
    __shared__ __align__(16) float wsm[404];
    __shared__ __align__(16) float gws[250];
    __shared__ int   cnt[NPG];
    __shared__ int   off[NPG];
    __shared__ int   pos[NPG];
    __shared__ int   psrc[EPG];
    __shared__ float pwt[EPG];
    __shared__ __align__(16) float agg[NPG * 8];
    __shared__ __align__(16) float h1s[NPG * 16];
    __shared__ __align__(16) float ps[NPG * 4];
    __shared__ __align__(16) float rrs[NPG * 4];

    const int t  = threadIdx.x;
    const int g0 = blockIdx.x * GPC;

    // stage conv weights: Wrel1@0(128) b1@128(16) Wroot1@144(128)
    //                     Wrel2@272(64) b2@336(4) Wroot2@340(64)
    if (t < 128) wsm[t]       = W_rel1[t];
    if (t < 16)  wsm[128 + t] = b1[t];
    if (t < 128) wsm[144 + t] = W_root1[t];
    if (t < 64)  wsm[272 + t] = W_rel2[t];
    if (t < 4)   wsm[336 + t] = b2[t];
    if (t < 64)  wsm[340 + t] = W_root2[t];
    // global-MLP weights: Wg1 80@0, bg1 8@80, Wg2 64@88, bg2 8@152,
    //                     Wg3 80@160, bg3 10@240
    if (t < 80)  gws[t]       = Wg1[t];
    if (t < 8)   gws[80 + t]  = bg1[t];
    if (t < 64)  gws[88 + t]  = Wg2[t];
    if (t < 8)   gws[152 + t] = bg2[t];
    if (t < 80)  gws[160 + t] = Wg3[t];
    if (t < 10)  gws[240 + t] = bg3[t];
    if (t < NPG) cnt[t] = 0;

    // ---- prefetch graph 0 ----
    if (t < NPG * 2) cpa16(&xbuf[0][t * 4], x + (size_t)g0 * NPG * 8 + t * 4);
    if (t < EPG / 4) {
        cpa16(&sbuf[0][t * 4], eidx + (size_t)g0 * EPG + t * 4);
        cpa16(&dbuf[0][t * 4], eidx + (size_t)EDGES_TOTAL + (size_t)g0 * EPG + t * 4);
        cpa16(&ebuf[0][t * 4], eattr + (size_t)g0 * EPG + t * 4);
    }
    CP_COMMIT();
    __syncthreads();   // weights staged

    // ---- one-shot global MLP for GPC graphs (threads 0..GPC*GLOB-1) ----
    if (t < GPC * GLOB) {
        const int gi = t / GLOB, o = t % GLOB;
        const float* gf = gfeat + (size_t)(g0 + gi) * GLOB;
        float gi_r[GLOB];
        #pragma unroll
        for (int i = 0; i < GLOB; i++) gi_r[i] = __ldg(gf + i);
        float a1[8];
        #pragma unroll
        for (int o1 = 0; o1 < 8; o1++) {
            float a = gws[80 + o1];
            #pragma unroll
            for (int i = 0; i < GLOB; i++) a += gi_r[i] * gws[i * 8 + o1];
            a1[o1] = fmaxf(a, 0.f);
        }
        float a2[8];
        #pragma unroll
        for (int o2 = 0; o2 < 8; o2++) {
            float a = gws[152 + o2];
            #pragma unroll
            for (int i = 0; i < 8; i++) a += a1[i] * gws[88 + i * 8 + o2];
            a2[o2] = fmaxf(a, 0.f);
        }
        float a = gws[240 + o];
        #pragma unroll
        for (int i = 0; i < 8; i++) a += a2[i] * gws[160 + i * 10 + o];
        g_concat[(size_t)(g0 + gi) * CPAD + NPG * 4 + o] = fmaxf(a, 0.f);
    }

    for (int it = 0; it < GPC; it++) {
        const int g = g0 + it;
        const int b = it & 1;
        const int base = g * NPG;

        CP_WAIT0();
        __syncthreads();

        if (it + 1 < GPC) {
            const int gn = g + 1, bn = b ^ 1;
            if (t < NPG * 2) cpa16(&xbuf[bn][t * 4], x + (size_t)gn * NPG * 8 + t * 4);
            if (t < EPG / 4) {
                cpa16(&sbuf[bn][t * 4], eidx + (size_t)gn * EPG + t * 4);
                cpa16(&dbuf[bn][t * 4], eidx + (size_t)EDGES_TOTAL + (size_t)gn * EPG + t * 4);
                cpa16(&ebuf[bn][t * 4], eattr + (size_t)gn * EPG + t * 4);
            }
            CP_COMMIT();
        }

        // ---- CSR 1: count in-degrees ----
        for (int e = t; e < EPG; e += 128)
            atomicAdd(&cnt[dbuf[b][e] - base], 1);
        __syncthreads();

        // ---- CSR 2: exclusive scan by warp 0 ----
        if (t < 32) {
            const unsigned m = 0xffffffffu;
            int c0 = cnt[t];
            int c1 = (t < NPG - 32) ? cnt[t + 32] : 0;
            int s0 = c0, s1 = c1;
            #pragma unroll
            for (int d2 = 1; d2 < 32; d2 <<= 1) {
                int n0 = __shfl_up_sync(m, s0, d2);
                int n1 = __shfl_up_sync(m, s1, d2);
                if (t >= d2) { s0 += n0; s1 += n1; }
            }
            int tot0 = __shfl_sync(m, s0, 31);
            s1 += tot0;
            int e0 = s0 - c0;
            off[t] = e0; pos[t] = e0;
            if (t < NPG - 32) {
                int e1 = s1 - c1;
                off[t + 32] = e1; pos[t + 32] = e1;
            }
        }
        __syncthreads();

        // ---- CSR 3: scatter (src, weight) ----
        for (int e = t; e < EPG; e += 128) {
            int d = dbuf[b][e] - base;
            int slot = atomicAdd(&pos[d], 1);
            psrc[slot] = sbuf[b][e] - base;
            pwt[slot]  = ebuf[b][e];
        }
        __syncthreads();

        // ---- gather 1: agg[v][0..7] = sum w * x[src] ----
        for (int item = t; item < NPG * 4; item += 128) {
            int v = item >> 2, fp = item & 3;
            int j0 = off[v];
            int j1 = (v < NPG - 1) ? off[v + 1] : EPG;
            u64 acc = pk(0.f, 0.f);
            for (int j = j0; j < j1; j++) {
                int s = psrc[j];
                float w = pwt[j];
                acc = f2fma(pk(w, w), *(const u64*)&xbuf[b][s * 8 + fp * 2], acc);
            }
            *(u64*)&agg[v * 8 + fp * 2] = acc;
        }
        __syncthreads();

        // ---- h1 = relu(agg@Wrel1 + b1 + x@Wroot1) ----
        for (int item = t; item < NPG * 8; item += 128) {
            int v = item >> 3, op2 = item & 7;
            u64 acc = *(const u64*)&wsm[128 + op2 * 2];
            #pragma unroll
            for (int c = 0; c < 8; c++) {
                float av = agg[v * 8 + c];
                float xv = xbuf[b][v * 8 + c];
                acc = f2fma(pk(av, av), *(const u64*)&wsm[c * 16 + op2 * 2], acc);
                acc = f2fma(pk(xv, xv), *(const u64*)&wsm[144 + c * 16 + op2 * 2], acc);
            }
            float lo, hi; upk(acc, lo, hi);
            h1s[v * 16 + op2 * 2]     = fmaxf(lo, 0.f);
            h1s[v * 16 + op2 * 2 + 1] = fmaxf(hi, 0.f);
        }
        if (t < NPG) cnt[t] = 0;
        __syncthreads();

        // ---- p = h1@Wrel2, rr = b2 + h1@Wroot2 ----
        for (int item = t; item < NPG * 2; item += 128) {
            int v = item >> 1, op2 = item & 1;
            u64 pa = pk(0.f, 0.f);
            u64 ra = *(const u64*)&wsm[336 + op2 * 2];
            #pragma unroll
            for (int c = 0; c < 16; c++) {
                float h = h1s[v * 16 + c];
                u64 hh = pk(h, h);
                pa = f2fma(hh, *(const u64*)&wsm[272 + c * 4 + op2 * 2], pa);
                ra = f2fma(hh, *(const u64*)&wsm[340 + c * 4 + op2 * 2], ra);
            }
            *(u64*)&ps[v * 4 + op2 * 2]  = pa;
            *(u64*)&rrs[v * 4 + op2 * 2] = ra;
        }
        __syncthreads();

        // ---- gather 2 + epilogue: h2 = relu(sum w*p[src] + rr) -> gmem ----
        float* opr = g_concat + (size_t)g * CPAD;
        for (int item = t; item < NPG * 2; item += 128) {
            int v = item >> 1, fp = item & 1;
            int j0 = off[v];
            int j1 = (v < NPG - 1) ? off[v + 1] : EPG;
            u64 acc = *(const u64*)&rrs[v * 4 + fp * 2];
            for (int j = j0; j < j1; j++) {
                int s = psrc[j];
                float w = pwt[j];
                acc = f2fma(pk(w, w), *(const u64*)&ps[s * 4 + fp * 2], acc);
            }
            float lo, hi; upk(acc, lo, hi);
            *(float2*)&opr[v * 4 + fp * 2]
                = make_float2(fmaxf(lo, 0.f), fmaxf(hi, 0.f));
        }
        // loop-top barrier orders everything for the next graph
    }
}

// ---------------------------------------------------------------------------
// Kernel B: out = sigmoid(relu(concat @ Wo1 + bo1) @ Wo2 + bo2)
// Streaming k-panel GEMM over padded K=240 (6 panels of 40), double-buffered
// cp.async, 256 threads. Warp owns 16 rows (8 f32x2 row-pairs), lane owns 4
// cols. 2 CTAs/SM.
// ---------------------------------------------------------------------------
__global__ __launch_bounds__(256) void mlp_kernel(
    const float* __restrict__ bo1, const float* __restrict__ Wo2,
    const float* __restrict__ bo2, float* __restrict__ out)
{
    extern __shared__ float sm[];
    float* wpan = sm;                    // [2][KP*128]
    float* ipan = sm + 2 * KP * 128;     // [2][128*KP]

    const int t  = threadIdx.x;
    const int g0 = blockIdx.x * TB;
    const int lane = t & 31;
    const int wp   = t >> 5;
    const int j0   = lane * 4;
    const int r0   = wp * 16;

    // issue panel p into buffer buf
    auto issue = [&](int p, int buf) {
        const float* wsrc = g_Wo1p + p * KP * 128;
        float* wdst = wpan + buf * KP * 128;
        #pragma unroll
        for (int i = t; i < KP * 128 / 4; i += 256)
            cpa16(&wdst[i * 4], wsrc + i * 4);
        float* idst = ipan + buf * TB * KP;
        #pragma unroll
        for (int i = t; i < TB * KP / 4; i += 256) {
            int r = i / (KP / 4), c4 = i % (KP / 4);
            cpa16(&idst[r * KP + c4 * 4],
                  g_concat + (size_t)(g0 + r) * CPAD + p * KP + c4 * 4);
        }
        CP_COMMIT();
    };

    issue(0, 0);

    u64 acc[8][4];
    #pragma unroll
    for (int pr = 0; pr < 8; pr++)
        #pragma unroll
        for (int c = 0; c < 4; c++) acc[pr][c] = pk(0.f, 0.f);

    for (int p = 0; p < NPAN; p++) {
        const int buf = p & 1;
        CP_WAIT0();
        __syncthreads();
        if (p + 1 < NPAN) issue(p + 1, buf ^ 1);   // overlaps compute below

        const float* W = wpan + buf * KP * 128;
        const float* I = ipan + buf * TB * KP;

        for (int k4 = 0; k4 < KP; k4 += 4) {
            float4 v4[16];
            #pragma unroll
            for (int r = 0; r < 16; r++)
                v4[r] = *(const float4*)&I[(r0 + r) * KP + k4];
            #pragma unroll
            for (int kk = 0; kk < 4; kk++) {
                const float4 w = *(const float4*)&W[(k4 + kk) * 128 + j0];
                const u64 wc0 = pk(w.x, w.x);
                const u64 wc1 = pk(w.y, w.y);
                const u64 wc2 = pk(w.z, w.z);
                const u64 wc3 = pk(w.w, w.w);
                #pragma unroll
                for (int pr = 0; pr < 8; pr++) {
                    const u64 vv = pk(((const float*)&v4[2 * pr])[kk],
                                      ((const float*)&v4[2 * pr + 1])[kk]);
                    acc[pr][0] = f2fma(vv, wc0, acc[pr][0]);
                    acc[pr][1] = f2fma(vv, wc1, acc[pr][1]);
                    acc[pr][2] = f2fma(vv, wc2, acc[pr][2]);
                    acc[pr][3] = f2fma(vv, wc3, acc[pr][3]);
                }
            }
        }
        __syncthreads();   // everyone done with buf before it is refilled
    }

    const float4 bv  = *(const float4*)&bo1[j0];
    const float4 wv  = *(const float4*)&Wo2[j0];
    const float bo2s = bo2[0];

    #pragma unroll
    for (int pr = 0; pr < 8; pr++) {
        float aA[4], aB[4];
        #pragma unroll
        for (int c = 0; c < 4; c++) upk(acc[pr][c], aA[c], aB[c]);
        float pA = fmaxf(aA[0] + bv.x, 0.f) * wv.x
                 + fmaxf(aA[1] + bv.y, 0.f) * wv.y
                 + fmaxf(aA[2] + bv.z, 0.f) * wv.z
                 + fmaxf(aA[3] + bv.w, 0.f) * wv.w;
        float pB = fmaxf(aB[0] + bv.x, 0.f) * wv.x
                 + fmaxf(aB[1] + bv.y, 0.f) * wv.y
                 + fmaxf(aB[2] + bv.z, 0.f) * wv.z
                 + fmaxf(aB[3] + bv.w, 0.f) * wv.w;
        #pragma unroll
        for (int off = 16; off; off >>= 1) {
            pA += __shfl_down_sync(0xffffffffu, pA, off);
            pB += __shfl_down_sync(0xffffffffu, pB, off);
        }
        if (lane == 0) {
            out[g0 + r0 + 2 * pr]     = 1.f / (1.f + expf(-(pA + bo2s)));
            out[g0 + r0 + 2 * pr + 1] = 1.f / (1.f + expf(-(pB + bo2s)));
        }
    }
}

// ---------------------------------------------------------------------------
extern "C" void kernel_launch(void* const* d_in, const int* in_sizes, int n_in,
                              void* d_out, int out_size)
{
    const float* x       = (const float*)d_in[0];
    const int*   eidx    = (const int*)  d_in[1];
    const float* eattr   = (const float*)d_in[2];
    const float* gfeat   = (const float*)d_in[3];
    const float* W_rel1  = (const float*)d_in[4];
    const float* b1      = (const float*)d_in[5];
    const float* W_root1 = (const float*)d_in[6];
    const float* W_rel2  = (const float*)d_in[7];
    const float* b2      = (const float*)d_in[8];
    const float* W_root2 = (const float*)d_in[9];
    const float* Wg1     = (const float*)d_in[10];
    const float* bg1     = (const float*)d_in[11];
    const float* Wg2     = (const float*)d_in[12];
    const float* bg2     = (const float*)d_in[13];
    const float* Wg3     = (const float*)d_in[14];
    const float* bg3     = (const float*)d_in[15];
    const float* Wo1     = (const float*)d_in[16];
    const float* bo1     = (const float*)d_in[17];
    const float* Wo2     = (const float*)d_in[18];
    const float* bo2     = (const float*)d_in[19];
    // d_in[20] = isTrain (eval mode: dropout is identity)

    padw_kernel<<<(226 * 128 + 255) / 256, 256>>>(Wo1);

    conv_kernel<<<BATCH / GPC, 128>>>(x, eidx, eattr, gfeat,
                                      W_rel1, b1, W_root1, W_rel2, b2, W_root2,
                                      Wg1, bg1, Wg2, bg2, Wg3, bg3);

    const int smem_bytes = (2 * KP * 128 + 2 * TB * KP) * (int)sizeof(float);
    cudaFuncSetAttribute(mlp_kernel, cudaFuncAttributeMaxDynamicSharedMemorySize,
                         smem_bytes);
    mlp_kernel<<<BATCH / TB, 256, smem_bytes>>>(bo1, Wo2, bo2, (float*)d_out);
}

// round 11
// speedup vs baseline: 1.5384x; 1.5384x over previous
#include <cuda_runtime.h>

#define BATCH  32768
#define NPG    54
#define EPG    144
#define GLOB   10
#define CONCAT 226
#define CPAD   228   // padded row stride (16B multiple) for g_concat
#define EDGES_TOTAL (BATCH*EPG)
#define TB     64    // rows per CTA in out-MLP GEMM
#define GPC    16    // graphs per conv CTA (32768 = 2048 * 16)

// Scratch for the [B, 228] padded concat activations (device global).
// Only columns [0,216) are written by conv; [216,226) computed inside mlp.
static __device__ __align__(16) float g_concat[(size_t)BATCH * CPAD];

typedef unsigned long long u64;

// ---------------- packed f32x2 helpers (sm_103a) ----------------
__device__ __forceinline__ u64 pk(float lo, float hi) {
    u64 r; asm("mov.b64 %0, {%1,%2};" : "=l"(r) : "f"(lo), "f"(hi)); return r;
}
__device__ __forceinline__ u64 f2fma(u64 a, u64 b, u64 c) {
    u64 d; asm("fma.rn.f32x2 %0, %1, %2, %3;" : "=l"(d) : "l"(a), "l"(b), "l"(c));
    return d;
}
__device__ __forceinline__ void upk(u64 v, float& lo, float& hi) {
    asm("mov.b64 {%0,%1}, %2;" : "=f"(lo), "=f"(hi) : "l"(v));
}

// ---------------- cp.async helpers ----------------
__device__ __forceinline__ void cpa16(void* s, const void* g) {
    unsigned ss = (unsigned)__cvta_generic_to_shared(s);
    asm volatile("cp.async.ca.shared.global [%0], [%1], 16;\n" :: "r"(ss), "l"(g));
}
#define CP_COMMIT() asm volatile("cp.async.commit_group;\n" ::: "memory")
#define CP_WAIT0()  asm volatile("cp.async.wait_group 0;\n" ::: "memory")

// ---------------------------------------------------------------------------
// Kernel A: persistent fused GraphConv1 -> relu -> GraphConv2 -> relu.
// 2048 CTAs x 128 threads, GPC=16 graphs each, cp.async double-buffered.
// CSR built once per graph; both aggregations are atomic-free gathers.
// Conv2 aggregates p = h1 @ W_rel2 (4-dim, linearity).
// ---------------------------------------------------------------------------
__global__ __launch_bounds__(128) void conv_kernel(
    const float* __restrict__ x,      const int*   __restrict__ eidx,
    const float* __restrict__ eattr,
    const float* __restrict__ W_rel1, const float* __restrict__ b1,
    const float* __restrict__ W_root1,
    const float* __restrict__ W_rel2, const float* __restrict__ b2,
    const float* __restrict__ W_root2)
{
    __shared__ __align__(16) float xbuf[2][NPG * 8];
    __shared__ __align__(16) int   sbuf[2][EPG];
    __shared__ __align__(16) int   dbuf[2][EPG];
    __shared__ __align__(16) float ebuf[2][EPG];
    __shared__ __align__(16) float wsm[404];
    __shared__ int   cnt[NPG];
    __shared__ int   off[NPG];
    __shared__ int   pos[NPG];
    __shared__ int   psrc[EPG];
    __shared__ float pwt[EPG];
    __shared__ __align__(16) float agg[NPG * 8];
    __shared__ __align__(16) float h1s[NPG * 16];
    __shared__ __align__(16) float ps[NPG * 4];
    __shared__ __align__(16) float rrs[NPG * 4];

    const int t = threadIdx.x;

    // stage weights once: Wrel1@0(128) b1@128(16) Wroot1@144(128)
    //                     Wrel2@272(64) b2@336(4) Wroot2@340(64)
    if (t < 128) wsm[t]       = W_rel1[t];
    if (t < 16)  wsm[128 + t] = b1[t];
    if (t < 128) wsm[144 + t] = W_root1[t];
    if (t < 64)  wsm[272 + t] = W_rel2[t];
    if (t < 4)   wsm[336 + t] = b2[t];
    if (t < 64)  wsm[340 + t] = W_root2[t];
    if (t < NPG) cnt[t] = 0;

    const int g0 = blockIdx.x * GPC;

    // ---- prefetch graph 0 ----
    if (t < NPG * 2) cpa16(&xbuf[0][t * 4], x + (size_t)g0 * NPG * 8 + t * 4);
    if (t < EPG / 4) {
        cpa16(&sbuf[0][t * 4], eidx + (size_t)g0 * EPG + t * 4);
        cpa16(&dbuf[0][t * 4], eidx + (size_t)EDGES_TOTAL + (size_t)g0 * EPG + t * 4);
        cpa16(&ebuf[0][t * 4], eattr + (size_t)g0 * EPG + t * 4);
    }
    CP_COMMIT();

    for (int it = 0; it < GPC; it++) {
        const int g = g0 + it;
        const int b = it & 1;
        const int base = g * NPG;

        CP_WAIT0();
        __syncthreads();                               // B-top

        // prefetch next graph into other buffer (overlaps with compute)
        if (it + 1 < GPC) {
            const int gn = g + 1, bn = b ^ 1;
            if (t < NPG * 2) cpa16(&xbuf[bn][t * 4], x + (size_t)gn * NPG * 8 + t * 4);
            if (t < EPG / 4) {
                cpa16(&sbuf[bn][t * 4], eidx + (size_t)gn * EPG + t * 4);
                cpa16(&dbuf[bn][t * 4], eidx + (size_t)EDGES_TOTAL + (size_t)gn * EPG + t * 4);
                cpa16(&ebuf[bn][t * 4], eattr + (size_t)gn * EPG + t * 4);
            }
            CP_COMMIT();
        }

        // ---- CSR 1: count in-degrees ----
        for (int e = t; e < EPG; e += 128)
            atomicAdd(&cnt[dbuf[b][e] - base], 1);
        __syncthreads();                               // B2

        // ---- CSR 2: exclusive scan by warp 0 (54 elems, 2 segments) ----
        if (t < 32) {
            const unsigned m = 0xffffffffu;
            int c0 = cnt[t];
            int c1 = (t < NPG - 32) ? cnt[t + 32] : 0;
            int s0 = c0, s1 = c1;
            #pragma unroll
            for (int d2 = 1; d2 < 32; d2 <<= 1) {
                int n0 = __shfl_up_sync(m, s0, d2);
                int n1 = __shfl_up_sync(m, s1, d2);
                if (t >= d2) { s0 += n0; s1 += n1; }
            }
            int tot0 = __shfl_sync(m, s0, 31);
            s1 += tot0;
            int e0 = s0 - c0;
            off[t] = e0; pos[t] = e0;
            if (t < NPG - 32) {
                int e1 = s1 - c1;
                off[t + 32] = e1; pos[t + 32] = e1;
            }
        }
        __syncthreads();                               // B3

        // ---- CSR 3: scatter (src, weight) into slots ----
        for (int e = t; e < EPG; e += 128) {
            int d = dbuf[b][e] - base;
            int slot = atomicAdd(&pos[d], 1);
            psrc[slot] = sbuf[b][e] - base;
            pwt[slot]  = ebuf[b][e];
        }
        __syncthreads();                               // B4

        // ---- gather 1: agg[v][0..7] = sum_{edges->v} w * x[src]  (f32x2) ----
        for (int item = t; item < NPG * 4; item += 128) {
            int v = item >> 2, fp = item & 3;
            int j0 = off[v];
            int j1 = (v < NPG - 1) ? off[v + 1] : EPG;
            u64 acc = pk(0.f, 0.f);
            for (int j = j0; j < j1; j++) {
                int s = psrc[j];
                float w = pwt[j];
                acc = f2fma(pk(w, w), *(const u64*)&xbuf[b][s * 8 + fp * 2], acc);
            }
            *(u64*)&agg[v * 8 + fp * 2] = acc;
        }
        __syncthreads();                               // B5

        // ---- h1 = relu(agg@Wrel1 + b1 + x@Wroot1) : f32x2, zero cnt ----
        for (int item = t; item < NPG * 8; item += 128) {
            int v = item >> 3, op2 = item & 7;        // output pair (2 of 16)
            u64 acc = *(const u64*)&wsm[128 + op2 * 2];
            #pragma unroll
            for (int c = 0; c < 8; c++) {
                float av = agg[v * 8 + c];
                float xv = xbuf[b][v * 8 + c];
                acc = f2fma(pk(av, av), *(const u64*)&wsm[c * 16 + op2 * 2], acc);
                acc = f2fma(pk(xv, xv), *(const u64*)&wsm[144 + c * 16 + op2 * 2], acc);
            }
            float lo, hi; upk(acc, lo, hi);
            h1s[v * 16 + op2 * 2]     = fmaxf(lo, 0.f);
            h1s[v * 16 + op2 * 2 + 1] = fmaxf(hi, 0.f);
        }
        if (t < NPG) cnt[t] = 0;                      // ready for next graph
        __syncthreads();                               // B6

        // ---- p = h1@Wrel2, rr = b2 + h1@Wroot2 : f32x2 ----
        for (int item = t; item < NPG * 2; item += 128) {
            int v = item >> 1, op2 = item & 1;        // pair of 4 outputs
            u64 pa = pk(0.f, 0.f);
            u64 ra = *(const u64*)&wsm[336 + op2 * 2];
            #pragma unroll
            for (int c = 0; c < 16; c++) {
                float h = h1s[v * 16 + c];
                u64 hh = pk(h, h);
                pa = f2fma(hh, *(const u64*)&wsm[272 + c * 4 + op2 * 2], pa);
                ra = f2fma(hh, *(const u64*)&wsm[340 + c * 4 + op2 * 2], ra);
            }
            *(u64*)&ps[v * 4 + op2 * 2]  = pa;
            *(u64*)&rrs[v * 4 + op2 * 2] = ra;
        }
        __syncthreads();                               // B7

        // ---- gather 2 + epilogue: h2 = relu(sum w*p[src] + rr) -> gmem ----
        float* opr = g_concat + (size_t)g * CPAD;
        for (int item = t; item < NPG * 2; item += 128) {
            int v = item >> 1, fp = item & 1;
            int j0 = off[v];
            int j1 = (v < NPG - 1) ? off[v + 1] : EPG;
            u64 acc = *(const u64*)&rrs[v * 4 + fp * 2];
            for (int j = j0; j < j1; j++) {
                int s = psrc[j];
                float w = pwt[j];
                acc = f2fma(pk(w, w), *(const u64*)&ps[s * 4 + fp * 2], acc);
            }
            float lo, hi; upk(acc, lo, hi);
            *(float2*)&opr[v * 4 + fp * 2]
                = make_float2(fmaxf(lo, 0.f), fmaxf(hi, 0.f));
        }
        // no barrier here: loop-top barrier orders everything
    }
}

// ---------------------------------------------------------------------------
// Kernel B: per-row global MLP (10->8->8->10) fused with
// out = sigmoid(relu(concat @ Wo1 + bo1) @ Wo2 + bo2).
// Full Wo1 (226x128) + 64 rows in smem. 256 threads: 8 warps, each warp owns
// 8 rows; lane owns 4 columns. Row values loaded as float4 across k (one
// LDS.128 per row per 4 k); weights one LDS.128 per warp per k.
// ---------------------------------------------------------------------------
__global__ __launch_bounds__(256) void mlp_kernel(
    const float* __restrict__ Wo1, const float* __restrict__ bo1,
    const float* __restrict__ Wo2, const float* __restrict__ bo2,
    const float* __restrict__ gfeat,
    const float* __restrict__ Wg1, const float* __restrict__ bg1,
    const float* __restrict__ Wg2, const float* __restrict__ bg2,
    const float* __restrict__ Wg3, const float* __restrict__ bg3,
    float* __restrict__ out)
{
    extern __shared__ float sm[];
    float* ws  = sm;                         // [226*128]
    float* ins = ws + CONCAT * 128;          // [64*228]
    float* gws = ins + TB * CPAD;            // [250] global-MLP weights
    float* gfs = gws + 256;                  // [64*10] global feats

    const int t  = threadIdx.x;
    const int g0 = blockIdx.x * TB;

    {
        const float4* wsrc = (const float4*)Wo1;
        float4*       wdst = (float4*)ws;
        for (int i = t; i < CONCAT * 128 / 4; i += 256) wdst[i] = wsrc[i];
        const float4* csrc = (const float4*)(g_concat + (size_t)g0 * CPAD);
        float4*       cdst = (float4*)ins;
        for (int i = t; i < TB * CPAD / 4; i += 256) cdst[i] = csrc[i];
        // global-MLP weights: Wg1 80@0, bg1 8@80, Wg2 64@88, bg2 8@152,
        //                     Wg3 80@160, bg3 10@240
        if (t < 80)  gws[t]       = Wg1[t];
        if (t < 8)   gws[80 + t]  = bg1[t];
        if (t < 64)  gws[88 + t]  = Wg2[t];
        if (t < 8)   gws[152 + t] = bg2[t];
        if (t < 80)  gws[160 + t] = Wg3[t];
        if (t < 10)  gws[240 + t] = bg3[t];
        // 64 rows x 10 global feats (640 floats, base g0*40B = 16B multiple)
        const float4* gsrc = (const float4*)(gfeat + (size_t)g0 * GLOB);
        float4*       gdst = (float4*)gfs;
        for (int i = t; i < TB * GLOB / 4; i += 256) gdst[i] = gsrc[i];
    }
    __syncthreads();

    // ---- per-row global MLP into ins[r*CPAD + 216..225] ----
    if (t < TB) {
        const float* gi = gfs + t * GLOB;
        float a1[8];
        #pragma unroll
        for (int o = 0; o < 8; o++) {
            float a = gws[80 + o];
            #pragma unroll
            for (int i = 0; i < GLOB; i++) a += gi[i] * gws[i * 8 + o];
            a1[o] = fmaxf(a, 0.f);
        }
        float a2[8];
        #pragma unroll
        for (int o = 0; o < 8; o++) {
            float a = gws[152 + o];
            #pragma unroll
            for (int i = 0; i < 8; i++) a += a1[i] * gws[88 + i * 8 + o];
            a2[o] = fmaxf(a, 0.f);
        }
        float* dst = ins + t * CPAD + NPG * 4;
        #pragma unroll
        for (int o = 0; o < GLOB; o++) {
            float a = gws[240 + o];
            #pragma unroll
            for (int i = 0; i < 8; i++) a += a2[i] * gws[160 + i * 10 + o];
            dst[o] = fmaxf(a, 0.f);
        }
    }
    __syncthreads();

    const int lane = t & 31;
    const int wp   = t >> 5;
    const int j0   = lane * 4;      // 4 output columns (2 f32x2 pairs)
    const int r0   = wp * 8;        // 8 rows per warp (8 warps x 8 = 64)

    u64 acc[8][2];
    #pragma unroll
    for (int r = 0; r < 8; r++) { acc[r][0] = pk(0.f, 0.f); acc[r][1] = pk(0.f, 0.f); }

    for (int kb = 0; kb < 224; kb += 4) {
        float4 v4[8];
        #pragma unroll
        for (int r = 0; r < 8; r++)
            v4[r] = *(const float4*)&ins[(r0 + r) * CPAD + kb];
        #pragma unroll
        for (int kk = 0; kk < 4; kk++) {
            const float4 w = *(const float4*)&ws[(kb + kk) * 128 + j0];
            const u64 w01 = pk(w.x, w.y);
            const u64 w23 = pk(w.z, w.w);
            #pragma unroll
            for (int r = 0; r < 8; r++) {
                const float v = ((const float*)&v4[r])[kk];
                const u64 vv = pk(v, v);
                acc[r][0] = f2fma(vv, w01, acc[r][0]);
                acc[r][1] = f2fma(vv, w23, acc[r][1]);
            }
        }
    }
    // remainder k = 224, 225
    #pragma unroll
    for (int k = 224; k < CONCAT; k++) {
        const float4 w = *(const float4*)&ws[k * 128 + j0];
        const u64 w01 = pk(w.x, w.y);
        const u64 w23 = pk(w.z, w.w);
        #pragma unroll
        for (int r = 0; r < 8; r++) {
            const float v = ins[(r0 + r) * CPAD + k];
            const u64 vv = pk(v, v);
            acc[r][0] = f2fma(vv, w01, acc[r][0]);
            acc[r][1] = f2fma(vv, w23, acc[r][1]);
        }
    }

    const float4 bv  = *(const float4*)&bo1[j0];
    const float4 wv  = *(const float4*)&Wo2[j0];
    const float bo2s = bo2[0];

    #pragma unroll
    for (int r = 0; r < 8; r++) {
        float a0, a1, a2, a3;
        upk(acc[r][0], a0, a1);
        upk(acc[r][1], a2, a3);
        float p = fmaxf(a0 + bv.x, 0.f) * wv.x
                + fmaxf(a1 + bv.y, 0.f) * wv.y
                + fmaxf(a2 + bv.z, 0.f) * wv.z
                + fmaxf(a3 + bv.w, 0.f) * wv.w;
        #pragma unroll
        for (int off = 16; off; off >>= 1)
            p += __shfl_down_sync(0xffffffffu, p, off);
        if (lane == 0)
            out[g0 + r0 + r] = 1.f / (1.f + expf(-(p + bo2s)));
    }
}

// ---------------------------------------------------------------------------
extern "C" void kernel_launch(void* const* d_in, const int* in_sizes, int n_in,
                              void* d_out, int out_size)
{
    const float* x       = (const float*)d_in[0];
    const int*   eidx    = (const int*)  d_in[1];
    const float* eattr   = (const float*)d_in[2];
    const float* gfeat   = (const float*)d_in[3];
    const float* W_rel1  = (const float*)d_in[4];
    const float* b1      = (const float*)d_in[5];
    const float* W_root1 = (const float*)d_in[6];
    const float* W_rel2  = (const float*)d_in[7];
    const float* b2      = (const float*)d_in[8];
    const float* W_root2 = (const float*)d_in[9];
    const float* Wg1     = (const float*)d_in[10];
    const float* bg1     = (const float*)d_in[11];
    const float* Wg2     = (const float*)d_in[12];
    const float* bg2     = (const float*)d_in[13];
    const float* Wg3     = (const float*)d_in[14];
    const float* bg3     = (const float*)d_in[15];
    const float* Wo1     = (const float*)d_in[16];
    const float* bo1     = (const float*)d_in[17];
    const float* Wo2     = (const float*)d_in[18];
    const float* bo2     = (const float*)d_in[19];
    // d_in[20] = isTrain (eval mode: dropout is identity)

    conv_kernel<<<BATCH / GPC, 128>>>(x, eidx, eattr,
                                      W_rel1, b1, W_root1, W_rel2, b2, W_root2);

    const int smem_bytes = (CONCAT * 128 + TB * CPAD + 256 + TB * GLOB)
                           * (int)sizeof(float);
    cudaFuncSetAttribute(mlp_kernel, cudaFuncAttributeMaxDynamicSharedMemorySize,
                         smem_bytes);
    mlp_kernel<<<BATCH / TB, 256, smem_bytes>>>(Wo1, bo1, Wo2, bo2,
                                                gfeat, Wg1, bg1, Wg2, bg2,
                                                Wg3, bg3, (float*)d_out);
}

// round 12
// speedup vs baseline: 1.6575x; 1.0774x over previous
#include <cuda_runtime.h>

#define BATCH  32768
#define NPG    54
#define EPG    144
#define GLOB   10
#define CONCAT 226
#define CPAD   240   // padded row stride; [226,240) always zero
#define EDGES_TOTAL (BATCH*EPG)
#define TB     64    // rows per CTA in out-MLP GEMM
#define GPC    16    // graphs per conv CTA (32768 = 2048 * 16)
#define KP     48    // k-panel (240 = 5 * 48)
#define NPAN   5

// [B, 240] padded concat activations (zero-init; [226,240) never written).
static __device__ __align__(16) float g_concat[(size_t)BATCH * CPAD];
// Zero-padded Wo1 [240][128]; rows [226,240) stay zero.
static __device__ __align__(16) float g_Wo1p[CPAD * 128];

typedef unsigned long long u64;

// ---------------- packed f32x2 helpers (sm_103a) ----------------
__device__ __forceinline__ u64 pk(float lo, float hi) {
    u64 r; asm("mov.b64 %0, {%1,%2};" : "=l"(r) : "f"(lo), "f"(hi)); return r;
}
__device__ __forceinline__ u64 f2fma(u64 a, u64 b, u64 c) {
    u64 d; asm("fma.rn.f32x2 %0, %1, %2, %3;" : "=l"(d) : "l"(a), "l"(b), "l"(c));
    return d;
}
__device__ __forceinline__ void upk(u64 v, float& lo, float& hi) {
    asm("mov.b64 {%0,%1}, %2;" : "=f"(lo), "=f"(hi) : "l"(v));
}

// ---------------- cp.async helpers ----------------
__device__ __forceinline__ void cpa16(void* s, const void* g) {
    unsigned ss = (unsigned)__cvta_generic_to_shared(s);
    asm volatile("cp.async.ca.shared.global [%0], [%1], 16;\n" :: "r"(ss), "l"(g));
}
#define CP_COMMIT() asm volatile("cp.async.commit_group;\n" ::: "memory")
#define CP_WAIT0()  asm volatile("cp.async.wait_group 0;\n" ::: "memory")

// ---------------------------------------------------------------------------
// Prologue: Wo1 -> zero-padded g_Wo1p (rows >= 226 remain zero). float4 copy.
// ---------------------------------------------------------------------------
__global__ __launch_bounds__(256) void padw_kernel(const float* __restrict__ Wo1)
{
    int i = blockIdx.x * 256 + threadIdx.x;          // float4 index
    if (i < 226 * 128 / 4)
        ((float4*)g_Wo1p)[i] = ((const float4*)Wo1)[i];
}

// ---------------------------------------------------------------------------
// Kernel A: persistent fused GraphConv1 -> relu -> GraphConv2 -> relu.
// Identical to the R11 champion except the g_concat row stride (240).
// ---------------------------------------------------------------------------
__global__ __launch_bounds__(128) void conv_kernel(
    const float* __restrict__ x,      const int*   __restrict__ eidx,
    const float* __restrict__ eattr,
    const float* __restrict__ W_rel1, const float* __restrict__ b1,
    const float* __restrict__ W_root1,
    const float* __restrict__ W_rel2, const float* __restrict__ b2,
    const float* __restrict__ W_root2)
{
    __shared__ __align__(16) float xbuf[2][NPG * 8];
    __shared__ __align__(16) int   sbuf[2][EPG];
    __shared__ __align__(16) int   dbuf[2][EPG];
    __shared__ __align__(16) float ebuf[2][EPG];
    __shared__ __align__(16) float wsm[404];
    __shared__ int   cnt[NPG];
    __shared__ int   off[NPG];
    __shared__ int   pos[NPG];
    __shared__ int   psrc[EPG];
    __shared__ float pwt[EPG];
    __shared__ __align__(16) float agg[NPG * 8];
    __shared__ __align__(16) float h1s[NPG * 16];
    __shared__ __align__(16) float ps[NPG * 4];
    __shared__ __align__(16) float rrs[NPG * 4];

    const int t = threadIdx.x;

    if (t < 128) wsm[t]       = W_rel1[t];
    if (t < 16)  wsm[128 + t] = b1[t];
    if (t < 128) wsm[144 + t] = W_root1[t];
    if (t < 64)  wsm[272 + t] = W_rel2[t];
    if (t < 4)   wsm[336 + t] = b2[t];
    if (t < 64)  wsm[340 + t] = W_root2[t];
    if (t < NPG) cnt[t] = 0;

    const int g0 = blockIdx.x * GPC;

    if (t < NPG * 2) cpa16(&xbuf[0][t * 4], x + (size_t)g0 * NPG * 8 + t * 4);
    if (t < EPG / 4) {
        cpa16(&sbuf[0][t * 4], eidx + (size_t)g0 * EPG + t * 4);
        cpa16(&dbuf[0][t * 4], eidx + (size_t)EDGES_TOTAL + (size_t)g0 * EPG + t * 4);
        cpa16(&ebuf[0][t * 4], eattr + (size_t)g0 * EPG + t * 4);
    }
    CP_COMMIT();

    for (int it = 0; it < GPC; it++) {
        const int g = g0 + it;
        const int b = it & 1;
        const int base = g * NPG;

        CP_WAIT0();
        __syncthreads();

        if (it + 1 < GPC) {
            const int gn = g + 1, bn = b ^ 1;
            if (t < NPG * 2) cpa16(&xbuf[bn][t * 4], x + (size_t)gn * NPG * 8 + t * 4);
            if (t < EPG / 4) {
                cpa16(&sbuf[bn][t * 4], eidx + (size_t)gn * EPG + t * 4);
                cpa16(&dbuf[bn][t * 4], eidx + (size_t)EDGES_TOTAL + (size_t)gn * EPG + t * 4);
                cpa16(&ebuf[bn][t * 4], eattr + (size_t)gn * EPG + t * 4);
            }
            CP_COMMIT();
        }

        // ---- CSR 1: count in-degrees ----
        for (int e = t; e < EPG; e += 128)
            atomicAdd(&cnt[dbuf[b][e] - base], 1);
        __syncthreads();

        // ---- CSR 2: exclusive scan by warp 0 ----
        if (t < 32) {
            const unsigned m = 0xffffffffu;
            int c0 = cnt[t];
            int c1 = (t < NPG - 32) ? cnt[t + 32] : 0;
            int s0 = c0, s1 = c1;
            #pragma unroll
            for (int d2 = 1; d2 < 32; d2 <<= 1) {
                int n0 = __shfl_up_sync(m, s0, d2);
                int n1 = __shfl_up_sync(m, s1, d2);
                if (t >= d2) { s0 += n0; s1 += n1; }
            }
            int tot0 = __shfl_sync(m, s0, 31);
            s1 += tot0;
            int e0 = s0 - c0;
            off[t] = e0; pos[t] = e0;
            if (t < NPG - 32) {
                int e1 = s1 - c1;
                off[t + 32] = e1; pos[t + 32] = e1;
            }
        }
        __syncthreads();

        // ---- CSR 3: scatter (src, weight) ----
        for (int e = t; e < EPG; e += 128) {
            int d = dbuf[b][e] - base;
            int slot = atomicAdd(&pos[d], 1);
            psrc[slot] = sbuf[b][e] - base;
            pwt[slot]  = ebuf[b][e];
        }
        __syncthreads();

        // ---- gather 1: agg[v][0..7] = sum w * x[src] ----
        for (int item = t; item < NPG * 4; item += 128) {
            int v = item >> 2, fp = item & 3;
            int j0 = off[v];
            int j1 = (v < NPG - 1) ? off[v + 1] : EPG;
            u64 acc = pk(0.f, 0.f);
            for (int j = j0; j < j1; j++) {
                int s = psrc[j];
                float w = pwt[j];
                acc = f2fma(pk(w, w), *(const u64*)&xbuf[b][s * 8 + fp * 2], acc);
            }
            *(u64*)&agg[v * 8 + fp * 2] = acc;
        }
        __syncthreads();

        // ---- h1 = relu(agg@Wrel1 + b1 + x@Wroot1) ----
        for (int item = t; item < NPG * 8; item += 128) {
            int v = item >> 3, op2 = item & 7;
            u64 acc = *(const u64*)&wsm[128 + op2 * 2];
            #pragma unroll
            for (int c = 0; c < 8; c++) {
                float av = agg[v * 8 + c];
                float xv = xbuf[b][v * 8 + c];
                acc = f2fma(pk(av, av), *(const u64*)&wsm[c * 16 + op2 * 2], acc);
                acc = f2fma(pk(xv, xv), *(const u64*)&wsm[144 + c * 16 + op2 * 2], acc);
            }
            float lo, hi; upk(acc, lo, hi);
            h1s[v * 16 + op2 * 2]     = fmaxf(lo, 0.f);
            h1s[v * 16 + op2 * 2 + 1] = fmaxf(hi, 0.f);
        }
        if (t < NPG) cnt[t] = 0;
        __syncthreads();

        // ---- p = h1@Wrel2, rr = b2 + h1@Wroot2 ----
        for (int item = t; item < NPG * 2; item += 128) {
            int v = item >> 1, op2 = item & 1;
            u64 pa = pk(0.f, 0.f);
            u64 ra = *(const u64*)&wsm[336 + op2 * 2];
            #pragma unroll
            for (int c = 0; c < 16; c++) {
                float h = h1s[v * 16 + c];
                u64 hh = pk(h, h);
                pa = f2fma(hh, *(const u64*)&wsm[272 + c * 4 + op2 * 2], pa);
                ra = f2fma(hh, *(const u64*)&wsm[340 + c * 4 + op2 * 2], ra);
            }
            *(u64*)&ps[v * 4 + op2 * 2]  = pa;
            *(u64*)&rrs[v * 4 + op2 * 2] = ra;
        }
        __syncthreads();

        // ---- gather 2 + epilogue: h2 -> g_concat ----
        float* opr = g_concat + (size_t)g * CPAD;
        for (int item = t; item < NPG * 2; item += 128) {
            int v = item >> 1, fp = item & 1;
            int j0 = off[v];
            int j1 = (v < NPG - 1) ? off[v + 1] : EPG;
            u64 acc = *(const u64*)&rrs[v * 4 + fp * 2];
            for (int j = j0; j < j1; j++) {
                int s = psrc[j];
                float w = pwt[j];
                acc = f2fma(pk(w, w), *(const u64*)&ps[s * 4 + fp * 2], acc);
            }
            float lo, hi; upk(acc, lo, hi);
            *(float2*)&opr[v * 4 + fp * 2]
                = make_float2(fmaxf(lo, 0.f), fmaxf(hi, 0.f));
        }
    }
}

// ---------------------------------------------------------------------------
// Kernel B: out = sigmoid(relu(concat @ Wo1 + bo1) @ Wo2 + bo2)
// K-panel streaming GEMM (5 panels of 48 over padded K=240), double-buffered
// cp.async for both Wo1 panels and input rows. 74.8 KB smem -> 3 CTAs/SM.
// 256 threads: 8 warps x 8 rows, lane owns 4 cols (2 f32x2 pairs).
// Global-MLP (10->8->8->10) computed lazily and patched into panel 4.
// ---------------------------------------------------------------------------
__global__ __launch_bounds__(256, 3) void mlp_kernel(
    const float* __restrict__ bo1, const float* __restrict__ Wo2,
    const float* __restrict__ bo2, const float* __restrict__ gfeat,
    const float* __restrict__ Wg1, const float* __restrict__ bg1,
    const float* __restrict__ Wg2, const float* __restrict__ bg2,
    const float* __restrict__ Wg3, const float* __restrict__ bg3,
    float* __restrict__ out)
{
    extern __shared__ float sm[];
    float* wpan = sm;                        // [2][KP*128]
    float* ipan = wpan + 2 * KP * 128;       // [2][TB*KP]
    float* gws  = ipan + 2 * TB * KP;        // [256] global-MLP weights

    const int t  = threadIdx.x;
    const int g0 = blockIdx.x * TB;
    const int lane = t & 31;
    const int wp   = t >> 5;
    const int j0   = lane * 4;
    const int r0   = wp * 8;

    // one-time: global-MLP weights into smem
    if (t < 80)  gws[t]       = Wg1[t];
    if (t < 8)   gws[80 + t]  = bg1[t];
    if (t < 64)  gws[88 + t]  = Wg2[t];
    if (t < 8)   gws[152 + t] = bg2[t];
    if (t < 80)  gws[160 + t] = Wg3[t];
    if (t < 10)  gws[240 + t] = bg3[t];

    auto issue = [&](int p, int buf) {
        // weight panel: contiguous 48*128 floats
        const float* wsrc = g_Wo1p + p * KP * 128;
        float* wdst = wpan + buf * KP * 128;
        for (int i = t; i < KP * 128 / 4; i += 256)
            cpa16(&wdst[i * 4], wsrc + i * 4);
        // input panel: 64 rows x 48 cols (12 float4 per row)
        float* idst = ipan + buf * TB * KP;
        for (int i = t; i < TB * KP / 4; i += 256) {
            int r = i / (KP / 4), c4 = i % (KP / 4);
            cpa16(&idst[r * KP + c4 * 4],
                  g_concat + (size_t)(g0 + r) * CPAD + p * KP + c4 * 4);
        }
        CP_COMMIT();
    };

    issue(0, 0);

    u64 acc[8][2];
    #pragma unroll
    for (int r = 0; r < 8; r++) { acc[r][0] = pk(0.f, 0.f); acc[r][1] = pk(0.f, 0.f); }

    for (int p = 0; p < NPAN; p++) {
        const int buf = p & 1;
        CP_WAIT0();
        __syncthreads();
        if (p + 1 < NPAN) issue(p + 1, buf ^ 1);

        if (p == NPAN - 1) {
            // patch global-MLP outputs into cols [216,226) of this panel
            // (panel 4 covers k = [192,240); local offset 216-192 = 24).
            if (t < TB) {
                const float* gf = gfeat + (size_t)(g0 + t) * GLOB;
                float gi[GLOB];
                #pragma unroll
                for (int i = 0; i < GLOB; i++) gi[i] = __ldg(gf + i);
                float a1[8];
                #pragma unroll
                for (int o = 0; o < 8; o++) {
                    float a = gws[80 + o];
                    #pragma unroll
                    for (int i = 0; i < GLOB; i++) a += gi[i] * gws[i * 8 + o];
                    a1[o] = fmaxf(a, 0.f);
                }
                float a2[8];
                #pragma unroll
                for (int o = 0; o < 8; o++) {
                    float a = gws[152 + o];
                    #pragma unroll
                    for (int i = 0; i < 8; i++) a += a1[i] * gws[88 + i * 8 + o];
                    a2[o] = fmaxf(a, 0.f);
                }
                float* dst = ipan + buf * TB * KP + t * KP + 24;
                #pragma unroll
                for (int o = 0; o < GLOB; o++) {
                    float a = gws[240 + o];
                    #pragma unroll
                    for (int i = 0; i < 8; i++) a += a2[i] * gws[160 + i * 10 + o];
                    dst[o] = fmaxf(a, 0.f);
                }
            }
            __syncthreads();
        }

        const float* W = wpan + buf * KP * 128;
        const float* I = ipan + buf * TB * KP;

        for (int k4 = 0; k4 < KP; k4 += 4) {
            float4 v4[8];
            #pragma unroll
            for (int r = 0; r < 8; r++)
                v4[r] = *(const float4*)&I[(r0 + r) * KP + k4];
            #pragma unroll
            for (int kk = 0; kk < 4; kk++) {
                const float4 w = *(const float4*)&W[(k4 + kk) * 128 + j0];
                const u64 w01 = pk(w.x, w.y);
                const u64 w23 = pk(w.z, w.w);
                #pragma unroll
                for (int r = 0; r < 8; r++) {
                    const float v = ((const float*)&v4[r])[kk];
                    const u64 vv = pk(v, v);
                    acc[r][0] = f2fma(vv, w01, acc[r][0]);
                    acc[r][1] = f2fma(vv, w23, acc[r][1]);
                }
            }
        }
        __syncthreads();   // all warps done with buf before refill
    }

    const float4 bv  = *(const float4*)&bo1[j0];
    const float4 wv  = *(const float4*)&Wo2[j0];
    const float bo2s = bo2[0];

    #pragma unroll
    for (int r = 0; r < 8; r++) {
        float a0, a1, a2, a3;
        upk(acc[r][0], a0, a1);
        upk(acc[r][1], a2, a3);
        float p = fmaxf(a0 + bv.x, 0.f) * wv.x
                + fmaxf(a1 + bv.y, 0.f) * wv.y
                + fmaxf(a2 + bv.z, 0.f) * wv.z
                + fmaxf(a3 + bv.w, 0.f) * wv.w;
        #pragma unroll
        for (int off = 16; off; off >>= 1)
            p += __shfl_down_sync(0xffffffffu, p, off);
        if (lane == 0)
            out[g0 + r0 + r] = 1.f / (1.f + expf(-(p + bo2s)));
    }
}

// ---------------------------------------------------------------------------
extern "C" void kernel_launch(void* const* d_in, const int* in_sizes, int n_in,
                              void* d_out, int out_size)
{
    const float* x       = (const float*)d_in[0];
    const int*   eidx    = (const int*)  d_in[1];
    const float* eattr   = (const float*)d_in[2];
    const float* gfeat   = (const float*)d_in[3];
    const float* W_rel1  = (const float*)d_in[4];
    const float* b1      = (const float*)d_in[5];
    const float* W_root1 = (const float*)d_in[6];
    const float* W_rel2  = (const float*)d_in[7];
    const float* b2      = (const float*)d_in[8];
    const float* W_root2 = (const float*)d_in[9];
    const float* Wg1     = (const float*)d_in[10];
    const float* bg1     = (const float*)d_in[11];
    const float* Wg2     = (const float*)d_in[12];
    const float* bg2     = (const float*)d_in[13];
    const float* Wg3     = (const float*)d_in[14];
    const float* bg3     = (const float*)d_in[15];
    const float* Wo1     = (const float*)d_in[16];
    const float* bo1     = (const float*)d_in[17];
    const float* Wo2     = (const float*)d_in[18];
    const float* bo2     = (const float*)d_in[19];
    // d_in[20] = isTrain (eval mode: dropout is identity)

    padw_kernel<<<(226 * 128 / 4 + 255) / 256, 256>>>(Wo1);

    conv_kernel<<<BATCH / GPC, 128>>>(x, eidx, eattr,
                                      W_rel1, b1, W_root1, W_rel2, b2, W_root2);

    const int smem_bytes = (2 * KP * 128 + 2 * TB * KP + 256) * (int)sizeof(float);
    cudaFuncSetAttribute(mlp_kernel, cudaFuncAttributeMaxDynamicSharedMemorySize,
                         smem_bytes);
    mlp_kernel<<<BATCH / TB, 256, smem_bytes>>>(bo1, Wo2, bo2,
                                                gfeat, Wg1, bg1, Wg2, bg2,
                                                Wg3, bg3, (float*)d_out);
}